// round 10
// baseline (speedup 1.0000x reference)
#include <cuda_runtime.h>

typedef unsigned long long ull;

#define CIN   6
#define COUT  16
#define HT    512
#define WD    512

#define TX    8           // threads.x
#define TY    16          // threads.y = tile height
#define PXT   8           // pixels per thread
#define TW    (TX*PXT)    // 64
#define TH    TY          // 16
#define SH    (TH+4)      // 20 halo rows
#define SWF   72          // padded plain row width (floats) = 18 chunks of 16B
#define NT    256
#define NTILE (8*32*32)   // 8192 tiles
#define NCTA  296         // 148 SMs * 2 CTAs

__device__ __forceinline__ ull pk(float lo, float hi) {
    ull r; asm("mov.b64 %0,{%1,%2};" : "=l"(r) : "f"(lo), "f"(hi)); return r;
}
__device__ __forceinline__ ull fma2(ull a, ull b, ull c) {
    ull d; asm("fma.rn.f32x2 %0,%1,%2,%3;" : "=l"(d) : "l"(a), "l"(b), "l"(c)); return d;
}
// 16B-chunk XOR swizzle: chunk k stored at position k ^ ((k>>3)&1)
__device__ __forceinline__ int swz(int k) { return k ^ ((k >> 3) & 1); }

// Balanced 2-coloring of the C3 table: every cin has exactly 5 live couts per half.
// half 0: {1,2,4,5,6,8,10,15}   half 1: {0,3,7,9,11,12,13,14}
__device__ const int d_LIVEG[2][CIN][5] = {
  {{4,5,6,10,15},{1,5,6,10,15},{1,2,6,8,15},{1,2,6,8,15},{2,4,8,10,15},{4,5,8,10,15}},
  {{0,9,11,12,14},{0,7,11,12,13},{0,7,11,13,14},{3,7,9,12,14},{3,7,9,12,13},{3,9,11,13,14}}};
__device__ constexpr int LIVEL[2][CIN][5] = {
  {{2,3,4,6,7},{0,3,4,6,7},{0,1,4,5,7},{0,1,4,5,7},{1,2,5,6,7},{2,3,5,6,7}},
  {{0,3,4,5,7},{0,2,4,5,6},{0,2,4,6,7},{1,2,3,5,7},{1,2,3,5,6},{1,3,4,6,7}}};
__device__ constexpr int HC[2][8] = {{1,2,4,5,6,8,10,15},{0,3,7,9,11,12,13,14}};

#define NWSM (2*CIN*5*5*6)   // [half][cin][dy][jj][dx pad6] = 1800 ulls

struct Smem {
    float sx[CIN][SH][SWF];   // plain halo tile, chunk-swizzled rows (34.6 KB)
    ull   wsm[NWSM];          // duplicated weight pairs (14.4 KB)
    float sb[COUT];
};

template<int HALF>
__device__ __forceinline__ void compute_half(
    Smem* s, float* __restrict__ out,
    int b, int h0, int w0, int tx, int ty,
    int cb0, int cb1, int cb2)
{
    ull acc[8][4];
#pragma unroll
    for (int l = 0; l < 8; l++) {
        float bv = s->sb[HC[HALF][l]];
        ull bb = pk(bv, bv);
#pragma unroll
        for (int p = 0; p < 4; p++) acc[l][p] = bb;
    }

#pragma unroll 1
    for (int dy = 0; dy < 5; dy++) {
        const float* rbase = &s->sx[0][ty + dy][0];
        const ull*   wdy   = s->wsm + dy * 30;
#pragma unroll
        for (int c = 0; c < CIN; c++) {
            const float* rp = rbase + c * (SH * SWF);
            float4 A = *reinterpret_cast<const float4*>(rp + cb0);
            float4 Bv = *reinterpret_cast<const float4*>(rp + cb1);
            float4 Cv = *reinterpret_cast<const float4*>(rp + cb2);
            // taps t[8tx + 0..11] = A.xyzw, Bv.xyzw, Cv.xyzw
            ull E[6] = { pk(A.x, A.y),  pk(A.z, A.w),  pk(Bv.x, Bv.y),
                         pk(Bv.z, Bv.w), pk(Cv.x, Cv.y), pk(Cv.z, Cv.w) };
            ull O[5] = { pk(A.y, A.z),  pk(A.w, Bv.x), pk(Bv.y, Bv.z),
                         pk(Bv.w, Cv.x), pk(Cv.y, Cv.z) };

            const ull* w = wdy + (HALF * CIN + c) * 150;
#pragma unroll
            for (int jj = 0; jj < 5; jj++) {
                ulonglong2 w01 = *reinterpret_cast<const ulonglong2*>(w + jj * 6);
                ulonglong2 w23 = *reinterpret_cast<const ulonglong2*>(w + jj * 6 + 2);
                ull        w4  = w[jj * 6 + 4];
                const int l = LIVEL[HALF][c][jj];
#pragma unroll
                for (int p = 0; p < 4; p++) {
                    acc[l][p] = fma2(E[p],     w01.x, acc[l][p]);
                    acc[l][p] = fma2(O[p],     w01.y, acc[l][p]);
                    acc[l][p] = fma2(E[p + 1], w23.x, acc[l][p]);
                    acc[l][p] = fma2(O[p + 1], w23.y, acc[l][p]);
                    acc[l][p] = fma2(E[p + 2], w4,    acc[l][p]);
                }
            }
        }
    }

    // Accumulator pairs are (out[2p], out[2p+1]) -> direct STG.128.
    const int hh = h0 + ty;
    const int ww = w0 + tx * PXT;
#pragma unroll
    for (int l = 0; l < 8; l++) {
        const int j = HC[HALF][l];
        ull* o = reinterpret_cast<ull*>(
            out + ((((size_t)b * COUT + j) * HT + hh) * WD + ww));
        *reinterpret_cast<ulonglong2*>(o)     = make_ulonglong2(acc[l][0], acc[l][1]);
        *reinterpret_cast<ulonglong2*>(o + 2) = make_ulonglong2(acc[l][2], acc[l][3]);
    }
}

__global__ __launch_bounds__(NT, 2)
void c3_conv_kernel(const float* __restrict__ x,
                    const float* __restrict__ Wt,
                    const float* __restrict__ bias,
                    float* __restrict__ out)
{
    extern __shared__ __align__(16) char smem_raw[];
    Smem* s = reinterpret_cast<Smem*>(smem_raw);

    const int tx = threadIdx.x, ty = threadIdx.y, tz = threadIdx.z;
    const int tid = tx + TX * ty + TX * TY * tz;

    // Stage weights ONCE per persistent CTA: duplicated (w,w) pairs,
    // [half][cin][dy][jj][dx pad 6].
    for (int i = tid; i < 2 * CIN * 5 * 5 * 5; i += NT) {
        int half = i / 750;
        int r = i - half * 750;
        int c  = r / 125; r -= c * 125;
        int dy = r / 25;  r -= dy * 25;
        int jj = r / 5;
        int dx = r - jj * 5;
        int j = d_LIVEG[half][c][jj];
        float wv = Wt[((j * CIN + c) * 5 + dy) * 5 + dx];
        s->wsm[(((half * CIN + c) * 5 + dy) * 5 + jj) * 6 + dx] = pk(wv, wv);
    }
    if (tid < COUT) s->sb[tid] = bias[tid];

    // Per-thread swizzled chunk offsets (floats) for the 3 input loads.
    const int cb0 = 4 * swz(2 * tx);
    const int cb1 = 4 * swz(2 * tx + 1);
    const int cb2 = 4 * swz(2 * tx + 2);

    for (int t = blockIdx.x; t < NTILE; t += NCTA) {
        const int wx = t & 7;
        const int hy = (t >> 3) & 31;
        const int b  = t >> 8;
        const int h0 = hy * TH;
        const int w0 = wx * TW;
        const float* xb = x + (size_t)b * CIN * HT * WD;

        // Build plain halo tile: task (c,row,kk) writes chunks 2kk (and 2kk+1 if <=16).
        // Chunk k = taps t[4k..4k+3], t[i] = x col (w0-2+i).
        // Interior: 3 aligned LDG.128 (A,B,C) -> register-select -> 2 STS.128.
        for (int u = tid; u < CIN * SH * 9; u += NT) {
            int c   = u / (SH * 9);
            int r2  = u - c * (SH * 9);
            int row = r2 / 9;
            int kk  = r2 - row * 9;
            int gr  = h0 - 2 + row;
            const float* rowp = xb + (size_t)c * HT * WD + (size_t)gr * WD;
            float* dst = &s->sx[c][row][0];
            int ca = w0 - 4 + 8 * kk;
            int hi = ca + ((kk < 8) ? 11 : 7);
            if ((unsigned)gr < HT && ca >= 0 && hi < WD) {
                float4 A = *reinterpret_cast<const float4*>(rowp + ca);
                float4 Bv = *reinterpret_cast<const float4*>(rowp + ca + 4);
                *reinterpret_cast<float4*>(dst + 4 * swz(2 * kk)) =
                    make_float4(A.z, A.w, Bv.x, Bv.y);
                if (kk < 8) {
                    float4 Cv = *reinterpret_cast<const float4*>(rowp + ca + 8);
                    *reinterpret_cast<float4*>(dst + 4 * swz(2 * kk + 1)) =
                        make_float4(Bv.z, Bv.w, Cv.x, Cv.y);
                }
            } else {
                bool grok = (unsigned)gr < HT;
#pragma unroll
                for (int kq = 0; kq < 2; kq++) {
                    int k = 2 * kk + kq;
                    if (k > 16) break;
                    float v[4];
#pragma unroll
                    for (int e = 0; e < 4; e++) {
                        int col = w0 - 2 + 4 * k + e;
                        v[e] = (grok && (unsigned)col < WD) ? rowp[col] : 0.0f;
                    }
                    *reinterpret_cast<float4*>(dst + 4 * swz(k)) =
                        make_float4(v[0], v[1], v[2], v[3]);
                }
            }
        }
        __syncthreads();

        if (tz == 0) compute_half<0>(s, out, b, h0, w0, tx, ty, cb0, cb1, cb2);
        else         compute_half<1>(s, out, b, h0, w0, tx, ty, cb0, cb1, cb2);
        __syncthreads();   // protect sx before next tile's build
    }
}

extern "C" void kernel_launch(void* const* d_in, const int* in_sizes, int n_in,
                              void* d_out, int out_size)
{
    (void)in_sizes; (void)n_in; (void)out_size;
    const float* x    = (const float*)d_in[0];
    const float* Wt   = (const float*)d_in[1];
    const float* bias = (const float*)d_in[2];
    // d_in[3] (mask) is the fixed LeNet C3 table, baked into the tables above.
    float* out = (float*)d_out;

    const int smem = (int)sizeof(Smem);
    cudaFuncSetAttribute(c3_conv_kernel,
                         cudaFuncAttributeMaxDynamicSharedMemorySize, smem);

    dim3 block(TX, TY, 2);
    dim3 grid(NCTA);
    c3_conv_kernel<<<grid, block, smem>>>(x, Wt, bias, out);
}